// round 8
// baseline (speedup 1.0000x reference)
#include <cuda_runtime.h>

// Problem constants
#define Bn  8
#define ICn 512
#define OCn 512
#define Hn  32
#define Wn  32

// RC_CONV = 1/sqrt(3*3*512), RC_DENSE = 1/sqrt(512)
#define RC_CONV_F  0.014731391274719963f
#define RC_CONV_SQ 2.170138888888889e-4f
#define RC_DENSE_F 0.04419417382415922f

// Scratch (allocation-free: __device__ globals)
__device__ float g_style[Bn * ICn];   // style[b, ic]
__device__ float g_s2[ICn * OCn];     // sum over 9 taps of conv_w^2
__device__ float g_demod[Bn * OCn];   // rsqrt demod factor

// ---------------------------------------------------------------------------
// style[b, j] = RC_DENSE * sum_ic w[b,ic]*dense_w[ic,j] + dense_b[j] + 1
// ---------------------------------------------------------------------------
__global__ void style_kernel(const float* __restrict__ w,
                             const float* __restrict__ dense_w,
                             const float* __restrict__ dense_b)
{
    __shared__ float ws[ICn];
    const int b = blockIdx.x;
    const int j = threadIdx.x;
    ws[j] = w[b * ICn + j];
    __syncthreads();
    float s = 0.f;
#pragma unroll 8
    for (int ic = 0; ic < ICn; ic++)
        s += ws[ic] * dense_w[ic * ICn + j];
    g_style[b * ICn + j] = s * RC_DENSE_F + dense_b[j] + 1.0f;
}

// ---------------------------------------------------------------------------
// s2[ic, oc] = sum_{t=0..8} conv_w[t, ic, oc]^2     (conv_w is [3,3,IC,OC])
// ---------------------------------------------------------------------------
__global__ void s2_kernel(const float* __restrict__ conv_w)
{
    const int ic = blockIdx.x;
    const int oc = threadIdx.x;
    float s = 0.f;
#pragma unroll
    for (int t = 0; t < 9; t++) {
        float v = conv_w[((size_t)t * ICn + ic) * OCn + oc];
        s += v * v;
    }
    g_s2[ic * OCn + oc] = s;
}

// ---------------------------------------------------------------------------
// demod[b, oc] = rsqrt(RC_CONV^2 * sum_ic style[b,ic]^2 * s2[ic,oc] + 1e-8)
// ---------------------------------------------------------------------------
__global__ void demod_kernel()
{
    __shared__ float st2[ICn];
    const int b  = blockIdx.x;
    const int oc = threadIdx.x;
    float v = g_style[b * ICn + threadIdx.x];
    st2[threadIdx.x] = v * v;
    __syncthreads();
    float s = 0.f;
#pragma unroll 8
    for (int ic = 0; ic < ICn; ic++)
        s += st2[ic] * g_s2[ic * OCn + oc];
    g_demod[b * OCn + oc] = rsqrtf(s * RC_CONV_SQ + 1e-8f);
}

// ---------------------------------------------------------------------------
// Main conv: y[b,oc,h,w] = RC_CONV * demod[b,oc] *
//     sum_{ic,kh,kw} (x[b,ic,h+kh-1,w+kw-1] * style[b,ic]) * conv_w[kh,kw,ic,oc]
//
// Implicit GEMM tiling:
//   block tile = 128 pixels (4 rows x 32 cols of one image) x 128 oc
//   256 threads, each an 8x8 register microtile (8 pixel-cols x 8 oc)
//   K chunk = 8 ic x 9 taps; sliding 10-wide x window shares loads across kw
// ---------------------------------------------------------------------------
__global__ __launch_bounds__(256, 2)
void conv_kernel(const float* __restrict__ x,
                 const float* __restrict__ conv_w,
                 float* __restrict__ out)
{
    const int oc0  = blockIdx.x * 128;   // 4 oc tiles
    const int row0 = blockIdx.y * 4;     // 8 row strips
    const int b    = blockIdx.z;         // 8 images

    __shared__ float xs[8][6][36];       // [ic][row0-1+r][col-1+c], style-scaled, zero-padded
    __shared__ float ws[72][128];        // [(kh*3+kw)*8 + ic][oc]

    const int tid   = threadIdx.x;
    const int tx    = tid & 15;          // oc fragment: oc0 + tx*8 .. +7
    const int ty    = tid >> 4;
    const int myrow = ty >> 2;           // 0..3  (pixel row within strip)
    const int mycol = (ty & 3) << 3;     // 0,8,16,24 (first of 8 pixel cols)

    float acc[8][8];
#pragma unroll
    for (int i = 0; i < 8; i++)
#pragma unroll
        for (int j = 0; j < 8; j++) acc[i][j] = 0.f;

    const float* stylep = g_style + b * ICn;
    const float* xb     = x + (size_t)b * ICn * Hn * Wn;

    for (int ic0 = 0; ic0 < ICn; ic0 += 8) {
        __syncthreads();

        // Load x tile (8 ic x 6 rows x 36 cols, halo + zero padding), style-scaled
        for (int idx = tid; idx < 8 * 6 * 36; idx += 256) {
            int ic  = idx / 216;
            int rem = idx - ic * 216;
            int r   = rem / 36;
            int c   = rem - r * 36;
            int gr  = row0 - 1 + r;
            int gc  = c - 1;
            float v = 0.f;
            if ((unsigned)gr < 32u && (unsigned)gc < 32u)
                v = xb[((ic0 + ic) * Hn + gr) * Wn + gc] * stylep[ic0 + ic];
            xs[ic][r][c] = v;
        }
        // Load weight tile (9 taps x 8 ic x 128 oc) vectorized
        for (int idx = tid; idx < 72 * 32; idx += 256) {
            int row = idx >> 5;          // tap*8 + ic
            int c4  = idx & 31;
            int tap = row >> 3;
            int ic  = row & 7;
            float4 v = *((const float4*)(conv_w + ((size_t)tap * ICn + ic0 + ic) * OCn + oc0) + c4);
            *((float4*)&ws[row][0] + c4) = v;
        }
        __syncthreads();

#pragma unroll
        for (int ic = 0; ic < 8; ic++) {
#pragma unroll
            for (int kh = 0; kh < 3; kh++) {
                float a[10];
#pragma unroll
                for (int u = 0; u < 10; u++) a[u] = xs[ic][myrow + kh][mycol + u];
#pragma unroll
                for (int kw = 0; kw < 3; kw++) {
                    float bf[8];
                    const float* wrow = &ws[(kh * 3 + kw) * 8 + ic][tx * 8];
                    *(float4*)&bf[0] = *(const float4*)&wrow[0];
                    *(float4*)&bf[4] = *(const float4*)&wrow[4];
#pragma unroll
                    for (int i = 0; i < 8; i++)
#pragma unroll
                        for (int j = 0; j < 8; j++)
                            acc[i][j] += a[i + kw] * bf[j];
                }
            }
        }
    }

    // Epilogue: scale by RC_CONV * demod[b, oc], vectorized stores
    const int gr = row0 + myrow;
#pragma unroll
    for (int j = 0; j < 8; j++) {
        int oc = oc0 + tx * 8 + j;
        float s = RC_CONV_F * g_demod[b * OCn + oc];
        float4 v0, v1;
        v0.x = acc[0][j] * s; v0.y = acc[1][j] * s;
        v0.z = acc[2][j] * s; v0.w = acc[3][j] * s;
        v1.x = acc[4][j] * s; v1.y = acc[5][j] * s;
        v1.z = acc[6][j] * s; v1.w = acc[7][j] * s;
        float* op = out + (((size_t)b * OCn + oc) * Hn + gr) * Wn + mycol;
        *(float4*)op       = v0;
        *(float4*)(op + 4) = v1;
    }
}

// ---------------------------------------------------------------------------
extern "C" void kernel_launch(void* const* d_in, const int* in_sizes, int n_in,
                              void* d_out, int out_size)
{
    const float* x       = (const float*)d_in[0];  // [8,512,32,32]
    const float* w       = (const float*)d_in[1];  // [8,512]
    const float* conv_w  = (const float*)d_in[2];  // [3,3,512,512]
    const float* dense_w = (const float*)d_in[3];  // [512,512]
    const float* dense_b = (const float*)d_in[4];  // [512]
    float* out = (float*)d_out;                    // [8,512,32,32]

    style_kernel<<<Bn, ICn>>>(w, dense_w, dense_b);
    s2_kernel<<<ICn, OCn>>>(conv_w);
    demod_kernel<<<Bn, OCn>>>();
    conv_kernel<<<dim3(4, 8, 8), 256>>>(x, conv_w, out);
}

// round 10
// speedup vs baseline: 1.7566x; 1.7566x over previous
#include <cuda_runtime.h>

// Problem constants
#define Bn  8
#define ICn 512
#define OCn 512
#define Hn  32
#define Wn  32

// RC_CONV = 1/sqrt(3*3*512), RC_DENSE = 1/sqrt(512)
#define RC_CONV_F  0.014731391274719963f
#define RC_CONV_SQ 2.170138888888889e-4f
#define RC_DENSE_F 0.04419417382415922f

// Scratch (allocation-free: __device__ globals)
__device__ float g_style[Bn * ICn];   // style[b, ic]
__device__ float g_s2[ICn * OCn];     // sum over 9 taps of conv_w^2
__device__ float g_demod[Bn * OCn];   // rsqrt demod factor

// ---------------------------------------------------------------------------
// style[b, j] = RC_DENSE * sum_ic w[b,ic]*dense_w[ic,j] + dense_b[j] + 1
// ---------------------------------------------------------------------------
__global__ void style_kernel(const float* __restrict__ w,
                             const float* __restrict__ dense_w,
                             const float* __restrict__ dense_b)
{
    __shared__ float wsh[ICn];
    const int b = blockIdx.x;
    const int j = threadIdx.x;
    wsh[j] = w[b * ICn + j];
    __syncthreads();
    float s = 0.f;
#pragma unroll 8
    for (int ic = 0; ic < ICn; ic++)
        s += wsh[ic] * dense_w[ic * ICn + j];
    g_style[b * ICn + j] = s * RC_DENSE_F + dense_b[j] + 1.0f;
}

// ---------------------------------------------------------------------------
// s2[ic, oc] = sum_{t=0..8} conv_w[t, ic, oc]^2     (conv_w is [3,3,IC,OC])
// ---------------------------------------------------------------------------
__global__ void s2_kernel(const float* __restrict__ conv_w)
{
    const int ic = blockIdx.x;
    const int oc = threadIdx.x;
    float s = 0.f;
#pragma unroll
    for (int t = 0; t < 9; t++) {
        float v = conv_w[((size_t)t * ICn + ic) * OCn + oc];
        s += v * v;
    }
    g_s2[ic * OCn + oc] = s;
}

// ---------------------------------------------------------------------------
// demod[b, oc] = rsqrt(RC_CONV^2 * sum_ic style[b,ic]^2 * s2[ic,oc] + 1e-8)
// ---------------------------------------------------------------------------
__global__ void demod_kernel()
{
    __shared__ float st2[ICn];
    const int b  = blockIdx.x;
    const int oc = threadIdx.x;
    float v = g_style[b * ICn + threadIdx.x];
    st2[threadIdx.x] = v * v;
    __syncthreads();
    float s = 0.f;
#pragma unroll 8
    for (int ic = 0; ic < ICn; ic++)
        s += st2[ic] * g_s2[ic * OCn + oc];
    g_demod[b * OCn + oc] = rsqrtf(s * RC_CONV_SQ + 1e-8f);
}

// ---------------------------------------------------------------------------
// Main conv: implicit GEMM with packed fp32x2 FMAs (fma.rn.f32x2).
//   block tile = 128 pixels (4 rows x 32 cols of one image) x 128 oc
//   256 threads, microtile = 8 pixels x 8 oc held as 8 x 4 packed (oc-pair) accs
//   x tile stored DUPLICATED as (v,v) float2 so the packed a-broadcast is a
//   single LDS.64; oc-pairs of w load directly as LDS.64 (no packing).
// Dynamic smem: xs2 [8][6][36] float2 (13824 B) + ws [72][128] float (36864 B)
// ---------------------------------------------------------------------------
#define XS2_ELEMS (8 * 6 * 36)
#define SMEM_XS2_BYTES (XS2_ELEMS * 8)
#define SMEM_WS_BYTES  (72 * 128 * 4)
#define SMEM_TOTAL_BYTES (SMEM_XS2_BYTES + SMEM_WS_BYTES)   // 50688

typedef unsigned long long ull;

union F2U { ull u; float2 f; };

__global__ __launch_bounds__(256, 2)
void conv_kernel(const float* __restrict__ x,
                 const float* __restrict__ conv_w,
                 float* __restrict__ out)
{
    extern __shared__ __align__(16) char smem_raw[];
    float2* xs2 = (float2*)smem_raw;                        // [ic][r][c] duplicated pairs
    float*  ws  = (float*)(smem_raw + SMEM_XS2_BYTES);      // [(tap)*8+ic][oc]

    const int oc0  = blockIdx.x * 128;   // 4 oc tiles
    const int row0 = blockIdx.y * 4;     // 8 row strips
    const int b    = blockIdx.z;         // 8 images

    const int tid   = threadIdx.x;
    const int tx    = tid & 15;          // oc fragment: oc0 + tx*8 .. +7
    const int ty    = tid >> 4;
    const int myrow = ty >> 2;           // 0..3  (pixel row within strip)
    const int mycol = (ty & 3) << 3;     // 0,8,16,24 (first of 8 pixel cols)

    // 8 pixels x 4 oc-pairs, packed f32x2 accumulators. 0ull == (0.f, 0.f)
    ull acc[8][4];
#pragma unroll
    for (int i = 0; i < 8; i++)
#pragma unroll
        for (int j2 = 0; j2 < 4; j2++) acc[i][j2] = 0ull;

    const float* stylep = g_style + b * ICn;
    const float* xb     = x + (size_t)b * ICn * Hn * Wn;

    for (int ic0 = 0; ic0 < ICn; ic0 += 8) {
        __syncthreads();

        // Load x tile (8 ic x 6 rows x 36 cols, halo + zero pad), style-scaled,
        // duplicated into both halves of a float2 for packed broadcast.
        for (int idx = tid; idx < XS2_ELEMS; idx += 256) {
            int ic  = idx / 216;
            int rem = idx - ic * 216;
            int r   = rem / 36;
            int c   = rem - r * 36;
            int gr  = row0 - 1 + r;
            int gc  = c - 1;
            float v = 0.f;
            if ((unsigned)gr < 32u && (unsigned)gc < 32u)
                v = xb[((ic0 + ic) * Hn + gr) * Wn + gc] * stylep[ic0 + ic];
            xs2[idx] = make_float2(v, v);
        }
        // Load weight tile (9 taps x 8 ic x 128 oc) vectorized
        for (int idx = tid; idx < 72 * 32; idx += 256) {
            int row = idx >> 5;          // tap*8 + ic
            int c4  = idx & 31;
            int tap = row >> 3;
            int ic  = row & 7;
            float4 v = *((const float4*)(conv_w + ((size_t)tap * ICn + ic0 + ic) * OCn + oc0) + c4);
            *((float4*)&ws[row * 128] + c4) = v;
        }
        __syncthreads();

#pragma unroll 4
        for (int ic = 0; ic < 8; ic++) {
#pragma unroll
            for (int kh = 0; kh < 3; kh++) {
                // 10-wide packed sliding window (each element = (v,v))
                ull av[10];
                const float2* xrow = xs2 + (ic * 6 + myrow + kh) * 36 + mycol;
#pragma unroll
                for (int u = 0; u < 10; u++)
                    av[u] = *(const ull*)(xrow + u);
#pragma unroll
                for (int kw = 0; kw < 3; kw++) {
                    const float* wrow = ws + ((kh * 3 + kw) * 8 + ic) * 128 + tx * 8;
                    ull bp[4];
#pragma unroll
                    for (int j2 = 0; j2 < 4; j2++)
                        bp[j2] = *(const ull*)(wrow + 2 * j2);
#pragma unroll
                    for (int i = 0; i < 8; i++)
#pragma unroll
                        for (int j2 = 0; j2 < 4; j2++)
                            asm("fma.rn.f32x2 %0, %1, %2, %0;"
                                : "+l"(acc[i][j2])
                                : "l"(av[i + kw]), "l"(bp[j2]));
                }
            }
        }
    }

    // Epilogue: scale by RC_CONV * demod[b, oc], vectorized stores
    const int gr = row0 + myrow;
#pragma unroll
    for (int j2 = 0; j2 < 4; j2++) {
        const int oc = oc0 + tx * 8 + 2 * j2;
        const float s0 = RC_CONV_F * g_demod[b * OCn + oc];
        const float s1 = RC_CONV_F * g_demod[b * OCn + oc + 1];
        float y0[8], y1[8];
#pragma unroll
        for (int i = 0; i < 8; i++) {
            F2U u; u.u = acc[i][j2];
            y0[i] = u.f.x * s0;
            y1[i] = u.f.y * s1;
        }
        float* op0 = out + (((size_t)b * OCn + oc) * Hn + gr) * Wn + mycol;
        float* op1 = op0 + (size_t)Hn * Wn;
        *(float4*)op0       = make_float4(y0[0], y0[1], y0[2], y0[3]);
        *(float4*)(op0 + 4) = make_float4(y0[4], y0[5], y0[6], y0[7]);
        *(float4*)op1       = make_float4(y1[0], y1[1], y1[2], y1[3]);
        *(float4*)(op1 + 4) = make_float4(y1[4], y1[5], y1[6], y1[7]);
    }
}

// ---------------------------------------------------------------------------
extern "C" void kernel_launch(void* const* d_in, const int* in_sizes, int n_in,
                              void* d_out, int out_size)
{
    const float* x       = (const float*)d_in[0];  // [8,512,32,32]
    const float* w       = (const float*)d_in[1];  // [8,512]
    const float* conv_w  = (const float*)d_in[2];  // [3,3,512,512]
    const float* dense_w = (const float*)d_in[3];  // [512,512]
    const float* dense_b = (const float*)d_in[4];  // [512]
    float* out = (float*)d_out;                    // [8,512,32,32]

    // Opt into >48KB dynamic smem (idempotent; attribute set, not an allocation)
    static int smem_set = 0;
    if (!smem_set) {
        cudaFuncSetAttribute(conv_kernel,
                             cudaFuncAttributeMaxDynamicSharedMemorySize,
                             SMEM_TOTAL_BYTES);
        smem_set = 1;
    }

    style_kernel<<<Bn, ICn>>>(w, dense_w, dense_b);
    s2_kernel<<<ICn, OCn>>>(conv_w);
    demod_kernel<<<Bn, OCn>>>();
    conv_kernel<<<dim3(4, 8, 8), 256, SMEM_TOTAL_BYTES>>>(x, conv_w, out);
}

// round 12
// speedup vs baseline: 3.7410x; 2.1297x over previous
#include <cuda_runtime.h>
#include <cstdint>

// Problem constants
#define Bn  8
#define ICn 512
#define OCn 512
#define Hn  32
#define Wn  32

// RC_CONV = 1/sqrt(3*3*512), RC_DENSE = 1/sqrt(512)
#define RC_CONV_F  0.014731391274719963f
#define RC_CONV_SQ 2.170138888888889e-4f
#define RC_DENSE_F 0.04419417382415922f

#define NCHUNK 72           // 9 taps x (512 ic / 64)
#define TILE_BYTES 16384    // 128 rows x 64 bf16 = 128 x 128B

// ---------------------------------------------------------------------------
// Scratch (allocation-free: __device__ globals)
// ---------------------------------------------------------------------------
__device__ float g_style[Bn * ICn];
__device__ float g_s2[ICn * OCn];
__device__ float g_demod[Bn * OCn];
// Pre-swizzled B tiles: [oc_tile(4)][chunk(72)][16KB], hi and lo bf16
__device__ __align__(16) unsigned char g_bpack_hi[4 * NCHUNK * TILE_BYTES];
__device__ __align__(16) unsigned char g_bpack_lo[4 * NCHUNK * TILE_BYTES];

// ---------------------------------------------------------------------------
// Helpers
// ---------------------------------------------------------------------------
__device__ __forceinline__ uint32_t smem_u32(const void* p) {
    uint32_t a;
    asm("{ .reg .u64 t; cvta.to.shared.u64 t, %1; cvt.u32.u64 %0, t; }" : "=r"(a) : "l"(p));
    return a;
}
__host__ __device__ __forceinline__ uint32_t sw128(uint32_t b) { return b ^ ((b >> 3) & 0x70); }

__device__ __forceinline__ void ldsm4(uint32_t a[4], uint32_t addr) {
    asm volatile("ldmatrix.sync.aligned.m8n8.x4.shared.b16 {%0,%1,%2,%3}, [%4];"
        : "=r"(a[0]), "=r"(a[1]), "=r"(a[2]), "=r"(a[3]) : "r"(addr));
}

#define MMA16816(c, a, b0v, b1v)                                                \
    asm volatile("mma.sync.aligned.m16n8k16.row.col.f32.bf16.bf16.f32 "         \
        "{%0,%1,%2,%3}, {%4,%5,%6,%7}, {%8,%9}, {%0,%1,%2,%3};"                 \
        : "+f"((c)[0]), "+f"((c)[1]), "+f"((c)[2]), "+f"((c)[3])                 \
        : "r"((a)[0]), "r"((a)[1]), "r"((a)[2]), "r"((a)[3]), "r"(b0v), "r"(b1v))

// Split f into bf16 hi (truncation) + bf16 lo (rounded residual), both packed x2
__device__ __forceinline__ void split2(float f0, float f1, uint32_t& hp, uint32_t& lp) {
    uint32_t u0 = __float_as_uint(f0), u1 = __float_as_uint(f1);
    hp = __byte_perm(u0, u1, 0x7632);                 // {lo16=hi(f0), hi16=hi(f1)}
    float l0 = f0 - __uint_as_float(u0 & 0xFFFF0000u);
    float l1 = f1 - __uint_as_float(u1 & 0xFFFF0000u);
    asm("cvt.rn.satfinite.bf16x2.f32 %0, %1, %2;" : "=r"(lp) : "f"(l1), "f"(l0));
}

// ---------------------------------------------------------------------------
// Prologue 1: style[b, j] = RC_DENSE * (w @ dense_w)[b,j] + dense_b[j] + 1
// ---------------------------------------------------------------------------
__global__ void style_kernel(const float* __restrict__ w,
                             const float* __restrict__ dense_w,
                             const float* __restrict__ dense_b)
{
    __shared__ float wsh[ICn];
    const int b = blockIdx.x, j = threadIdx.x;
    wsh[j] = w[b * ICn + j];
    __syncthreads();
    float s = 0.f;
#pragma unroll 8
    for (int ic = 0; ic < ICn; ic++) s += wsh[ic] * dense_w[ic * ICn + j];
    g_style[b * ICn + j] = s * RC_DENSE_F + dense_b[j] + 1.0f;
}

// Prologue 2: s2[ic, oc] = sum_taps conv_w^2
__global__ void s2_kernel(const float* __restrict__ conv_w)
{
    const int ic = blockIdx.x, oc = threadIdx.x;
    float s = 0.f;
#pragma unroll
    for (int t = 0; t < 9; t++) {
        float v = conv_w[((size_t)t * ICn + ic) * OCn + oc];
        s += v * v;
    }
    g_s2[ic * OCn + oc] = s;
}

// Prologue 3: demod[b, oc]
__global__ void demod_kernel()
{
    __shared__ float st2[ICn];
    const int b = blockIdx.x, oc = threadIdx.x;
    float v = g_style[b * ICn + threadIdx.x];
    st2[threadIdx.x] = v * v;
    __syncthreads();
    float s = 0.f;
#pragma unroll 8
    for (int ic = 0; ic < ICn; ic++) s += st2[ic] * g_s2[ic * OCn + oc];
    g_demod[b * OCn + oc] = rsqrtf(s * RC_CONV_SQ + 1e-8f);
}

// ---------------------------------------------------------------------------
// Prologue 4: pre-pack B tiles in the SW128 K-contiguous smem image.
// Tile (oc_tile, chunk): row n = oc-oc0 (128 rows), col kk = ic-ic0 (64 bf16).
// byte = n*128 + kk*2, then sw128 (XOR of 16B-chunk index with n&7).
// ---------------------------------------------------------------------------
__global__ void bpack_kernel(const float* __restrict__ conv_w)
{
    const int oct = blockIdx.x, chunk = blockIdx.y;
    const int tap = chunk >> 3, ic0 = (chunk & 7) << 6;
    const int oc0 = oct << 7;
    const size_t toff = ((size_t)oct * NCHUNK + chunk) * TILE_BYTES;
#pragma unroll
    for (int it = 0; it < 4; it++) {
        int idx = threadIdx.x + it * 256;
        int n = idx & 127, q = idx >> 7;          // q = 16B chunk (8 bf16) index
        uint32_t hp[4], lp[4];
#pragma unroll
        for (int j2 = 0; j2 < 4; j2++) {
            int ic = ic0 + q * 8 + 2 * j2;
            float f0 = conv_w[((size_t)tap * ICn + ic)     * OCn + oc0 + n];
            float f1 = conv_w[((size_t)tap * ICn + ic + 1) * OCn + oc0 + n];
            split2(f0, f1, hp[j2], lp[j2]);
        }
        uint32_t sw = sw128((uint32_t)(n * 128 + q * 16));
        *(uint4*)(g_bpack_hi + toff + sw) = make_uint4(hp[0], hp[1], hp[2], hp[3]);
        *(uint4*)(g_bpack_lo + toff + sw) = make_uint4(lp[0], lp[1], lp[2], lp[3]);
    }
}

// ---------------------------------------------------------------------------
// Main conv: bf16 hi/lo-split implicit GEMM on legacy tensor cores (mma.sync).
//   CTA: M=128 px (4 rows x 32 cols of one image) x N=128 oc.
//   8 warps = 4(M) x 2(N); warp tile 32x64; 64 fp32 accums/thread.
//   72 chunks; per chunk: build A hi/lo (im2col + style + split), copy
//   pre-packed B hi/lo, then 4 k16-steps of ldmatrix + 3-way split MMAs.
// smem: A_hi 16K | A_lo 16K | B_hi 16K | B_lo 16K = 64KB dynamic
// ---------------------------------------------------------------------------
#define SM_AHI 0
#define SM_ALO 16384
#define SM_BHI 32768
#define SM_BLO 49152
#define SM_TOTAL 65536

__global__ __launch_bounds__(256, 2)
void conv_tc_kernel(const float* __restrict__ x, float* __restrict__ out)
{
    extern __shared__ __align__(16) char sm[];
    const uint32_t smb = smem_u32(sm);

    const int tid  = threadIdx.x;
    const int lane = tid & 31;
    const int wid  = tid >> 5;
    const int warpM = wid >> 1;          // 0..3 -> pixel row within strip
    const int warpN = wid & 1;           // 0..1 -> 64-oc half

    const int oc0  = blockIdx.x << 7;
    const int row0 = blockIdx.y << 2;
    const int b    = blockIdx.z;
    const float* xb     = x + (size_t)b * ICn * Hn * Wn;
    const float* stylep = g_style + b * ICn;

    // ldmatrix per-thread address pieces (K-contiguous, sw128)
    const uint32_t rbyte = (uint32_t)(lane & 15) * 128u;
    const uint32_t kxor  = (uint32_t)(lane & 7) << 4;
    const uint32_t ksel  = (uint32_t)(lane & 16);
    const uint32_t aBase = smb + SM_AHI + (uint32_t)(warpM * 32) * 128u + rbyte;
    const uint32_t bBase = smb + SM_BHI + (uint32_t)(warpN * 64) * 128u + rbyte;

    float c[2][8][4];
#pragma unroll
    for (int mi = 0; mi < 2; mi++)
#pragma unroll
        for (int nj = 0; nj < 8; nj++)
#pragma unroll
            for (int q = 0; q < 4; q++) c[mi][nj][q] = 0.f;

    for (int chunk = 0; chunk < NCHUNK; chunk++) {
        const int tap = chunk >> 3;
        const int ic0 = (chunk & 7) << 6;
        const int kh  = tap / 3, kw = tap - 3 * kh;

        __syncthreads();
        // ---- Build A hi/lo (128 px x 64 bf16), im2col + style scale + split
#pragma unroll
        for (int it = 0; it < 4; it++) {
            int idx = tid + it * 256;
            int m = idx & 127, q = idx >> 7;
            int r = m >> 5, ccol = m & 31;
            int gr = row0 + r + kh - 1;
            int gc = ccol + kw - 1;
            bool ok = ((unsigned)gr < 32u) && ((unsigned)gc < 32u);
            const int icb = ic0 + q * 8;
            uint32_t hp[4], lp[4];
#pragma unroll
            for (int j2 = 0; j2 < 4; j2++) {
                int ic = icb + 2 * j2;
                float f0 = 0.f, f1 = 0.f;
                if (ok) {
                    f0 = xb[((size_t)ic * Hn + gr) * Wn + gc]       * stylep[ic];
                    f1 = xb[((size_t)(ic + 1) * Hn + gr) * Wn + gc] * stylep[ic + 1];
                }
                split2(f0, f1, hp[j2], lp[j2]);
            }
            uint32_t sw = sw128((uint32_t)(m * 128 + q * 16));
            *(uint4*)(sm + SM_AHI + sw) = make_uint4(hp[0], hp[1], hp[2], hp[3]);
            *(uint4*)(sm + SM_ALO + sw) = make_uint4(lp[0], lp[1], lp[2], lp[3]);
        }
        // ---- Copy pre-packed B hi/lo (straight 16KB copies, L2-resident)
        {
            const size_t toff = ((size_t)blockIdx.x * NCHUNK + chunk) * TILE_BYTES;
            const uint4* bh = (const uint4*)(g_bpack_hi + toff);
            const uint4* bl = (const uint4*)(g_bpack_lo + toff);
            uint4* sh = (uint4*)(sm + SM_BHI);
            uint4* sl = (uint4*)(sm + SM_BLO);
#pragma unroll
            for (int i = tid; i < 1024; i += 256) { sh[i] = bh[i]; sl[i] = bl[i]; }
        }
        __syncthreads();

        // ---- MMA mainloop: 4 k16 steps
#pragma unroll
        for (int ks = 0; ks < 4; ks++) {
            const uint32_t col = ((uint32_t)(ks * 32) + ksel) ^ kxor;
            uint32_t ah[2][4], al[2][4];
            ldsm4(ah[0], aBase + col);
            ldsm4(ah[1], aBase + 2048 + col);
            ldsm4(al[0], aBase + 16384 + col);
            ldsm4(al[1], aBase + 16384 + 2048 + col);
#pragma unroll
            for (int j16 = 0; j16 < 4; j16++) {
                uint32_t bh[4], bl[4];
                ldsm4(bh, bBase + (uint32_t)(j16 * 2048) + col);
                ldsm4(bl, bBase + 16384 + (uint32_t)(j16 * 2048) + col);
                // B reg layout: frag(n0-7)={r0,r2}, frag(n8-15)={r1,r3}
#pragma unroll
                for (int mi = 0; mi < 2; mi++) {
                    MMA16816(c[mi][j16 * 2],     ah[mi], bh[0], bh[2]);   // hi*hi
                    MMA16816(c[mi][j16 * 2],     al[mi], bh[0], bh[2]);   // lo*hi
                    MMA16816(c[mi][j16 * 2],     ah[mi], bl[0], bl[2]);   // hi*lo
                    MMA16816(c[mi][j16 * 2 + 1], ah[mi], bh[1], bh[3]);
                    MMA16816(c[mi][j16 * 2 + 1], al[mi], bh[1], bh[3]);
                    MMA16816(c[mi][j16 * 2 + 1], ah[mi], bl[1], bl[3]);
                }
            }
        }
    }

    // ---- Epilogue: demod scale + direct stores from register accumulators
    const int gr = row0 + warpM;
    const int g  = lane >> 2;
    const int nq = (lane & 3) * 2;
#pragma unroll
    for (int nj = 0; nj < 8; nj++) {
        const int oc = oc0 + warpN * 64 + nj * 8 + nq;
        const float s0 = RC_CONV_F * g_demod[b * OCn + oc];
        const float s1 = RC_CONV_F * g_demod[b * OCn + oc + 1];
#pragma unroll
        for (int mi = 0; mi < 2; mi++) {
            float* op = out + (((size_t)b * OCn + oc) * Hn + gr) * Wn
                            + warpM * 0 + mi * 16 + g;   // px col = mi*16+g
            op[0]        = c[mi][nj][0] * s0;
            op[1024]     = c[mi][nj][1] * s1;   // oc+1: stride H*W = 1024 floats
            op[8]        = c[mi][nj][2] * s0;
            op[1032]     = c[mi][nj][3] * s1;
        }
    }
}

// ---------------------------------------------------------------------------
extern "C" void kernel_launch(void* const* d_in, const int* in_sizes, int n_in,
                              void* d_out, int out_size)
{
    const float* x       = (const float*)d_in[0];  // [8,512,32,32]
    const float* w       = (const float*)d_in[1];  // [8,512]
    const float* conv_w  = (const float*)d_in[2];  // [3,3,512,512]
    const float* dense_w = (const float*)d_in[3];  // [512,512]
    const float* dense_b = (const float*)d_in[4];  // [512]
    float* out = (float*)d_out;                    // [8,512,32,32]

    static int smem_set = 0;
    if (!smem_set) {
        cudaFuncSetAttribute(conv_tc_kernel,
                             cudaFuncAttributeMaxDynamicSharedMemorySize, SM_TOTAL);
        smem_set = 1;
    }

    style_kernel<<<Bn, ICn>>>(w, dense_w, dense_b);
    s2_kernel<<<ICn, OCn>>>(conv_w);
    demod_kernel<<<Bn, OCn>>>();
    bpack_kernel<<<dim3(4, NCHUNK), 256>>>(conv_w);
    conv_tc_kernel<<<dim3(4, 8, 8), 256, SM_TOTAL>>>(x, out);
}